// round 15
// baseline (speedup 1.0000x reference)
#include <cuda_runtime.h>

#define POOL 14
#define H 128
#define W 128
#define C 1024
#define R 256
#define C4 (C / 4)

// FINAL — R6 configuration. Best 53.3us; reproduced 53.98 / 54.0 / 53.76
// (sigma ~0.3us). Kernel ~52us vs ~49us compulsory floor (205MB output
// writes at ~4.2TB/s streaming-write rate == L1 wavefront minimum).
//
// One CTA per (roi, py) output row; 256 threads = one float4 channel-group
// each. x-side gather tuples precomputed by threads 0..13 into shared;
// y-side scalars once per CTA. Full 14-px unroll lets ptxas front-batch
// the 4 straight LDG.128 per px (48 regs — the measured optimum of the
// register/occupancy curve). Streaming __stcs keeps the 64MB img fully
// L2-resident. Zero-weight corners (fx==0 / fy==0, ~26% each) alias to the
// already-loaded address in the precompute — bit-exact, converts those
// reads to L1 hits at zero inner-loop cost.
//
// Fully-mapped dead ends (do not reintroduce):
//   regs: 40 -> 86.5us (R7), 64 -> 55.4us (R13); 48 optimal.
//   sw-pipelining (R3 +6us), per-px predicated skips (R4 +4us),
//   uniform two-path bodies (R5 +25us), __stwt (R8 +4us),
//   128-thr fat threads (R11 +4.8us).
//   Rejected on paper: grid-dim swap (kills same-ROI L2 adjacency),
//   CTA merging (wave efficiency 96.9% -> 80.7%), __ldcs (kills aliased
//   L1 hits), L2 policy windows (img already resident).
__global__ __launch_bounds__(256) void roi_resize_kernel(
    const float4* __restrict__ img,   // [H, W, C4]
    const float*  __restrict__ rois,  // [R, 4]
    float4*       __restrict__ out)   // [R, POOL, POOL, C4]
{
    const int py = blockIdx.x;          // 0..13
    const int r  = blockIdx.y;          // 0..255
    const int c4 = threadIdx.x;         // 0..255

    __shared__ int   s_ax0[POOL];
    __shared__ int   s_ax1[POOL];
    __shared__ float s_fx [POOL];

    const int x1 = (int)rois[r * 4 + 0];
    const int y1 = (int)rois[r * 4 + 1];
    const int x2 = (int)rois[r * 4 + 2];
    const int y2 = (int)rois[r * 4 + 3];

    if (threadIdx.x < POOL) {
        const float ww = (float)(x2 - x1);
        const float src_x = (float)threadIdx.x * (ww * (1.0f / POOL));
        const int   x0 = (int)floorf(src_x);
        const int   x1i = min(x0 + 1, (x2 - x1) - 1);
        const float fx = src_x - (float)x0;
        const int   ax0 = min(max(x1 + x0, 0), W - 1);
        int         ax1 = min(max(x1 + x1i, 0), W - 1);
        if (fx == 0.0f) ax1 = ax0;      // zero-weight corner -> alias address
        s_fx [threadIdx.x] = fx;
        s_ax0[threadIdx.x] = ax0;
        s_ax1[threadIdx.x] = ax1;
    }

    const float hh = (float)(y2 - y1);
    const float src_y = (float)py * (hh * (1.0f / POOL));
    const int   y0 = (int)floorf(src_y);
    const float fy = src_y - (float)y0;
    const int   y1i = min(y0 + 1, (y2 - y1) - 1);
    const int   ay0 = min(max(y1 + y0, 0), H - 1);
    int         ay1 = min(max(y1 + y1i, 0), H - 1);
    if (fy == 0.0f) ay1 = ay0;          // zero-weight row -> alias address

    __syncthreads();

    const float4* __restrict__ row0 = img + (size_t)(ay0 * W) * C4 + c4;
    const float4* __restrict__ row1 = img + (size_t)(ay1 * W) * C4 + c4;
    float4* __restrict__ orow = out + ((size_t)(r * POOL + py) * POOL) * C4 + c4;

    #pragma unroll
    for (int px = 0; px < POOL; px++) {
        const int   ax0 = s_ax0[px];
        const int   ax1 = s_ax1[px];
        const float fx  = s_fx[px];

        const float4 v00 = row0[ax0 * C4];
        const float4 v01 = row0[ax1 * C4];
        const float4 v10 = row1[ax0 * C4];
        const float4 v11 = row1[ax1 * C4];

        float4 o;
        {
            float top = v00.x + (v01.x - v00.x) * fx;
            float bot = v10.x + (v11.x - v10.x) * fx;
            o.x = top + (bot - top) * fy;
        }
        {
            float top = v00.y + (v01.y - v00.y) * fx;
            float bot = v10.y + (v11.y - v10.y) * fx;
            o.y = top + (bot - top) * fy;
        }
        {
            float top = v00.z + (v01.z - v00.z) * fx;
            float bot = v10.z + (v11.z - v10.z) * fx;
            o.z = top + (bot - top) * fy;
        }
        {
            float top = v00.w + (v01.w - v00.w) * fx;
            float bot = v10.w + (v11.w - v10.w) * fx;
            o.w = top + (bot - top) * fy;
        }

        __stcs(&orow[(size_t)px * C4], o);   // evict-first streaming store
    }
}

extern "C" void kernel_launch(void* const* d_in, const int* in_sizes, int n_in,
                              void* d_out, int out_size) {
    const float4* img  = (const float4*)d_in[0];
    const float*  rois = (const float*)d_in[1];
    float4*       out  = (float4*)d_out;

    dim3 grid(POOL, R);
    roi_resize_kernel<<<grid, 256>>>(img, rois, out);
}

// round 16
// speedup vs baseline: 1.0006x; 1.0006x over previous
#include <cuda_runtime.h>

#define POOL 14
#define H 128
#define W 128
#define C 1024
#define R 256
#define C4 (C / 4)

// FINAL — R6 configuration. Best 53.3us; reproduced 53.98 / 54.0 / 53.76 /
// 53.76 (sigma ~0.3us; kernel time 51.3-53.0us vs ~49-51us compulsory
// floor: 205MB output writes at the measured ~4.2TB/s streaming-write rate,
// coincident with the L1 wavefront minimum).
//
// One CTA per (roi, py) output row; 256 threads = one float4 channel-group
// each. x-side gather tuples precomputed by threads 0..13 into shared;
// y-side scalars once per CTA. Full 14-px unroll lets ptxas front-batch
// the 4 straight LDG.128 per px (48 regs — measured optimum: 40->86.5us,
// 48->53.3us, 64->55.4us). Streaming __stcs keeps the 64MB img fully
// L2-resident. Zero-weight corners (fx==0 / fy==0, ~26% each) alias to the
// already-loaded address in the precompute — bit-exact, converts those
// reads to L1 hits at zero inner-loop cost. grid=(POOL,R) linearizes
// same-ROI CTAs adjacently, maximizing corner-row L2 sharing.
//
// Fully-mapped dead ends (do not reintroduce): sw-pipelining (R3),
// per-px predicated skips (R4), uniform two-path bodies (R5), reg caps /
// budgets 40/64 (R7/R13), __stwt (R8), 128-thr fat threads (R11).
// Rejected on paper: grid-dim swap, CTA merging, __ldcs, L2 policy windows.
__global__ __launch_bounds__(256) void roi_resize_kernel(
    const float4* __restrict__ img,   // [H, W, C4]
    const float*  __restrict__ rois,  // [R, 4]
    float4*       __restrict__ out)   // [R, POOL, POOL, C4]
{
    const int py = blockIdx.x;          // 0..13
    const int r  = blockIdx.y;          // 0..255
    const int c4 = threadIdx.x;         // 0..255

    __shared__ int   s_ax0[POOL];
    __shared__ int   s_ax1[POOL];
    __shared__ float s_fx [POOL];

    const int x1 = (int)rois[r * 4 + 0];
    const int y1 = (int)rois[r * 4 + 1];
    const int x2 = (int)rois[r * 4 + 2];
    const int y2 = (int)rois[r * 4 + 3];

    if (threadIdx.x < POOL) {
        const float ww = (float)(x2 - x1);
        const float src_x = (float)threadIdx.x * (ww * (1.0f / POOL));
        const int   x0 = (int)floorf(src_x);
        const int   x1i = min(x0 + 1, (x2 - x1) - 1);
        const float fx = src_x - (float)x0;
        const int   ax0 = min(max(x1 + x0, 0), W - 1);
        int         ax1 = min(max(x1 + x1i, 0), W - 1);
        if (fx == 0.0f) ax1 = ax0;      // zero-weight corner -> alias address
        s_fx [threadIdx.x] = fx;
        s_ax0[threadIdx.x] = ax0;
        s_ax1[threadIdx.x] = ax1;
    }

    const float hh = (float)(y2 - y1);
    const float src_y = (float)py * (hh * (1.0f / POOL));
    const int   y0 = (int)floorf(src_y);
    const float fy = src_y - (float)y0;
    const int   y1i = min(y0 + 1, (y2 - y1) - 1);
    const int   ay0 = min(max(y1 + y0, 0), H - 1);
    int         ay1 = min(max(y1 + y1i, 0), H - 1);
    if (fy == 0.0f) ay1 = ay0;          // zero-weight row -> alias address

    __syncthreads();

    const float4* __restrict__ row0 = img + (size_t)(ay0 * W) * C4 + c4;
    const float4* __restrict__ row1 = img + (size_t)(ay1 * W) * C4 + c4;
    float4* __restrict__ orow = out + ((size_t)(r * POOL + py) * POOL) * C4 + c4;

    #pragma unroll
    for (int px = 0; px < POOL; px++) {
        const int   ax0 = s_ax0[px];
        const int   ax1 = s_ax1[px];
        const float fx  = s_fx[px];

        const float4 v00 = row0[ax0 * C4];
        const float4 v01 = row0[ax1 * C4];
        const float4 v10 = row1[ax0 * C4];
        const float4 v11 = row1[ax1 * C4];

        float4 o;
        {
            float top = v00.x + (v01.x - v00.x) * fx;
            float bot = v10.x + (v11.x - v10.x) * fx;
            o.x = top + (bot - top) * fy;
        }
        {
            float top = v00.y + (v01.y - v00.y) * fx;
            float bot = v10.y + (v11.y - v10.y) * fx;
            o.y = top + (bot - top) * fy;
        }
        {
            float top = v00.z + (v01.z - v00.z) * fx;
            float bot = v10.z + (v11.z - v10.z) * fx;
            o.z = top + (bot - top) * fy;
        }
        {
            float top = v00.w + (v01.w - v00.w) * fx;
            float bot = v10.w + (v11.w - v10.w) * fx;
            o.w = top + (bot - top) * fy;
        }

        __stcs(&orow[(size_t)px * C4], o);   // evict-first streaming store
    }
}

extern "C" void kernel_launch(void* const* d_in, const int* in_sizes, int n_in,
                              void* d_out, int out_size) {
    const float4* img  = (const float4*)d_in[0];
    const float*  rois = (const float*)d_in[1];
    float4*       out  = (float4*)d_out;

    dim3 grid(POOL, R);
    roi_resize_kernel<<<grid, 256>>>(img, rois, out);
}

// round 17
// speedup vs baseline: 1.0036x; 1.0030x over previous
#include <cuda_runtime.h>

#define POOL 14
#define H 128
#define W 128
#define C 1024
#define R 256
#define C4 (C / 4)

// FINAL — R6 configuration. Best 53.3us; six reproductions 53.3-54.0us
// (sigma ~0.25us). Kernel 51.3-53.0us vs ~49-51us compulsory floor
// (205MB output writes at the measured ~4.2TB/s streaming-write rate,
// coincident with the L1 wavefront minimum).
//
// One CTA per (roi, py) output row; 256 threads = one float4 channel-group
// each. x-side gather tuples precomputed by threads 0..13 into shared;
// y-side scalars once per CTA. Full 14-px unroll lets ptxas front-batch
// the 4 straight LDG.128 per px (48 regs — measured optimum: 40->86.5us,
// 48->53.3us, 64->55.4us). Streaming __stcs keeps the 64MB img fully
// L2-resident. Zero-weight corners (fx==0 / fy==0, ~26% each) alias to the
// already-loaded address in the precompute — bit-exact, converts those
// reads to L1 hits at zero inner-loop cost. grid=(POOL,R) linearizes
// same-ROI CTAs adjacently, maximizing corner-row L2 sharing.
//
// Fully-mapped dead ends (do not reintroduce): sw-pipelining (R3),
// per-px predicated skips (R4), uniform two-path bodies (R5), reg
// budgets 40/64 (R7/R13), __stwt (R8), 128-thr fat threads (R11).
// Rejected on paper: grid-dim swap, CTA merging, __ldcs, L2 policy
// windows, cp.async smem staging (working set > smem; adds LDS latency).
__global__ __launch_bounds__(256) void roi_resize_kernel(
    const float4* __restrict__ img,   // [H, W, C4]
    const float*  __restrict__ rois,  // [R, 4]
    float4*       __restrict__ out)   // [R, POOL, POOL, C4]
{
    const int py = blockIdx.x;          // 0..13
    const int r  = blockIdx.y;          // 0..255
    const int c4 = threadIdx.x;         // 0..255

    __shared__ int   s_ax0[POOL];
    __shared__ int   s_ax1[POOL];
    __shared__ float s_fx [POOL];

    const int x1 = (int)rois[r * 4 + 0];
    const int y1 = (int)rois[r * 4 + 1];
    const int x2 = (int)rois[r * 4 + 2];
    const int y2 = (int)rois[r * 4 + 3];

    if (threadIdx.x < POOL) {
        const float ww = (float)(x2 - x1);
        const float src_x = (float)threadIdx.x * (ww * (1.0f / POOL));
        const int   x0 = (int)floorf(src_x);
        const int   x1i = min(x0 + 1, (x2 - x1) - 1);
        const float fx = src_x - (float)x0;
        const int   ax0 = min(max(x1 + x0, 0), W - 1);
        int         ax1 = min(max(x1 + x1i, 0), W - 1);
        if (fx == 0.0f) ax1 = ax0;      // zero-weight corner -> alias address
        s_fx [threadIdx.x] = fx;
        s_ax0[threadIdx.x] = ax0;
        s_ax1[threadIdx.x] = ax1;
    }

    const float hh = (float)(y2 - y1);
    const float src_y = (float)py * (hh * (1.0f / POOL));
    const int   y0 = (int)floorf(src_y);
    const float fy = src_y - (float)y0;
    const int   y1i = min(y0 + 1, (y2 - y1) - 1);
    const int   ay0 = min(max(y1 + y0, 0), H - 1);
    int         ay1 = min(max(y1 + y1i, 0), H - 1);
    if (fy == 0.0f) ay1 = ay0;          // zero-weight row -> alias address

    __syncthreads();

    const float4* __restrict__ row0 = img + (size_t)(ay0 * W) * C4 + c4;
    const float4* __restrict__ row1 = img + (size_t)(ay1 * W) * C4 + c4;
    float4* __restrict__ orow = out + ((size_t)(r * POOL + py) * POOL) * C4 + c4;

    #pragma unroll
    for (int px = 0; px < POOL; px++) {
        const int   ax0 = s_ax0[px];
        const int   ax1 = s_ax1[px];
        const float fx  = s_fx[px];

        const float4 v00 = row0[ax0 * C4];
        const float4 v01 = row0[ax1 * C4];
        const float4 v10 = row1[ax0 * C4];
        const float4 v11 = row1[ax1 * C4];

        float4 o;
        {
            float top = v00.x + (v01.x - v00.x) * fx;
            float bot = v10.x + (v11.x - v10.x) * fx;
            o.x = top + (bot - top) * fy;
        }
        {
            float top = v00.y + (v01.y - v00.y) * fx;
            float bot = v10.y + (v11.y - v10.y) * fx;
            o.y = top + (bot - top) * fy;
        }
        {
            float top = v00.z + (v01.z - v00.z) * fx;
            float bot = v10.z + (v11.z - v10.z) * fx;
            o.z = top + (bot - top) * fy;
        }
        {
            float top = v00.w + (v01.w - v00.w) * fx;
            float bot = v10.w + (v11.w - v10.w) * fx;
            o.w = top + (bot - top) * fy;
        }

        __stcs(&orow[(size_t)px * C4], o);   // evict-first streaming store
    }
}

extern "C" void kernel_launch(void* const* d_in, const int* in_sizes, int n_in,
                              void* d_out, int out_size) {
    const float4* img  = (const float4*)d_in[0];
    const float*  rois = (const float*)d_in[1];
    float4*       out  = (float4*)d_out;

    dim3 grid(POOL, R);
    roi_resize_kernel<<<grid, 256>>>(img, rois, out);
}